// round 14
// baseline (speedup 1.0000x reference)
#include <cuda_runtime.h>
#include <cuda_fp16.h>
#include <cstdint>
#include <cstddef>

#define HH 384
#define WW 384
#define BATCH 4
#define HWSZ (HH * WW)

// h1/h2: plain fp16 activations, layout [b][c][y][x]
__device__ __half g_h1[(size_t)BATCH * 64 * HWSZ];
__device__ __half g_h2[(size_t)BATCH * 64 * HWSZ];
__device__ float  g_logits[(size_t)BATCH * 81 * HWSZ];

// =============================== helpers ====================================
__device__ __forceinline__ uint32_t smem_u32(const void* p) {
    uint32_t a;
    asm("{ .reg .u64 t; cvta.to.shared.u64 t, %1; cvt.u32.u64 %0, t; }"
        : "=r"(a) : "l"(p));
    return a;
}
__device__ __forceinline__ void ldmx4(uint32_t& r0, uint32_t& r1, uint32_t& r2,
                                      uint32_t& r3, uint32_t addr) {
    asm volatile("ldmatrix.sync.aligned.m8n8.x4.shared.b16 {%0,%1,%2,%3}, [%4];"
                 : "=r"(r0), "=r"(r1), "=r"(r2), "=r"(r3) : "r"(addr));
}
__device__ __forceinline__ void ldmx2(uint32_t& r0, uint32_t& r1, uint32_t addr) {
    asm volatile("ldmatrix.sync.aligned.m8n8.x2.shared.b16 {%0,%1}, [%2];"
                 : "=r"(r0), "=r"(r1) : "r"(addr));
}
__device__ __forceinline__ void mma16816(float* c, const uint32_t* a,
                                         uint32_t b0, uint32_t b1) {
    asm volatile(
        "mma.sync.aligned.m16n8k16.row.col.f32.f16.f16.f32 "
        "{%0,%1,%2,%3}, {%4,%5,%6,%7}, {%8,%9}, {%0,%1,%2,%3};"
        : "+f"(c[0]), "+f"(c[1]), "+f"(c[2]), "+f"(c[3])
        : "r"(a[0]), "r"(a[1]), "r"(a[2]), "r"(a[3]), "r"(b0), "r"(b1));
}
__device__ __forceinline__ uint32_t packh2(float f0, float f1) {
    uint32_t h;
    asm("cvt.rn.f16x2.f32 %0, %1, %2;" : "=r"(h) : "f"(f1), "f"(f0));
    return h;
}

// ===================== HMMA implicit-GEMM 3x3 conv ==========================
// Single-fp16 products. Per CTA: co-slice M=32, px-tile N=128, RPC=32 rows,
// 8 rows per mainloop iteration over a 10-plane SMEM ring.
// 512 threads / 16 warps: warp wx = 8-px slice, each warp does the FULL M=32
// (mt=0,1), so every B fragment feeds 2 co-halves x dy-overlap, and every A
// fragment feeds 8 rows.
#define RPC 32
#define RPI 8
#define NPX 128
#define A_PLANE (9 * 32 * 128)             // 36864 (fp16 weights)
#define OFF_B   A_PLANE
#define B_PLANE (132 * 128)                // 16896 per slot
#define NSLOT 10
#define HMMA_SMEM (OFF_B + NSLOT * B_PLANE)  // 205824
#define NTHREADS 512
#define NWARPS 16

template <int COUT, int NSLICE, bool RELU, bool PACK_OUT>
__global__ __launch_bounds__(NTHREADS, 1)
void conv3x3_hmma(const __half* __restrict__ in, const float* __restrict__ wgt,
                  const float* __restrict__ bias, void* __restrict__ outv) {
    extern __shared__ __align__(128) char smem[];
    const uint32_t sb = smem_u32(smem);
    const int tid = threadIdx.x, warp = tid >> 5, lane = tid & 31;
    const int x0 = blockIdx.x * NPX;
    const int y0 = blockIdx.y * RPC;
    const int mslice = blockIdx.z % NSLICE;
    const int b = blockIdx.z / NSLICE;
    const int co_base = mslice * 32;
    const int wx = warp;          // px slice (8)

    // ---- stage A: 9 taps x 32 co x 64 ci fp16, swizzled [co][ci] ----
    {
        const int cpl = lane & 3, po = lane >> 2;
        for (int it = warp; it < 288; it += NWARPS) {
            int t = it / 32, r = it & 31;
            int cotile = r >> 3, c = r & 7;
            int co = cotile * 8 + po;
            int ci0 = c * 8 + cpl * 2;
            int cog = co_base + co;
            float f0 = 0.f, f1 = 0.f;
            if (cog < COUT) {
                const float* wp = wgt + ((size_t)cog * 64 + ci0) * 9 + t;
                f0 = __ldg(wp);
                f1 = __ldg(wp + 9);
            }
            uint32_t h = packh2(f0, f1);
            uint32_t off = (uint32_t)((t * 32 + co) * 128 +
                                      ((c ^ (co & 7)) << 4) + cpl * 4);
            asm volatile("st.shared.b32 [%0], %1;" :: "r"(sb + off), "r"(h) : "memory");
        }
    }

    // ---- B row-plane stage: plane row yy -> slot (yy+400)%NSLOT ----
    auto stage_B = [&](int yy) {
        const int slot = (yy + 400) % NSLOT;
        const bool ok_row = (yy >= 0) && (yy < HH);
        const unsigned short* src = reinterpret_cast<const unsigned short*>(
            in + ((size_t)b * 64 * HH + (ok_row ? yy : 0)) * WW);
        const int cpl = lane & 3, po = lane >> 2;
        const uint32_t bH = sb + OFF_B + slot * B_PLANE;
        for (int it = warp; it < 136; it += NWARPS) {
            int c = it & 7, pxt = it >> 3;
            int px = pxt * 8 + po;
            if (px >= 132) continue;
            int ci0 = c * 8 + cpl * 2;
            int gx = x0 - 1 + px;
            bool ok = ok_row && (gx >= 0) && (gx < WW);
            const unsigned short* p = src + (size_t)ci0 * HWSZ + (ok ? gx : 0);
            uint32_t s0 = ok ? (uint32_t)__ldg(p) : 0u;
            uint32_t s1 = ok ? (uint32_t)__ldg(p + HWSZ) : 0u;
            uint32_t hi = s0 | (s1 << 16);
            uint32_t off = (uint32_t)(px * 128 + ((c ^ (px & 7)) << 4) + cpl * 4);
            asm volatile("st.shared.b32 [%0], %1;" :: "r"(bH + off), "r"(hi) : "memory");
        }
    };

    // initial fill: planes y0-1 .. y0+8
    for (int i = -1; i <= 8; i++) stage_B(y0 + i);
    __syncthreads();

    const int r7 = lane & 7, g = lane >> 3;
    const int a_row0 = r7 + ((g & 1) << 3);   // row within a 16-co tile
    const int a_kh = g >> 1;
    const int b_noff = r7;
    const int b_kh = g & 1;
    const int nb = wx * 8;
    const int row_d = lane >> 2, col_d = (lane & 3) * 2;

    const int yend = y0 + RPC;
#pragma unroll 1
    for (int y = y0; y < yend; y += RPI) {
        float acc[RPI][2][4];
#pragma unroll
        for (int r = 0; r < RPI; r++)
#pragma unroll
            for (int m = 0; m < 2; m++)
#pragma unroll
                for (int j = 0; j < 4; j++) acc[r][m][j] = 0.f;

        // plane slots: index i = input row (y-1+i), i=0..9
        uint32_t plH[NSLOT];
#pragma unroll
        for (int i = 0; i < NSLOT; i++)
            plH[i] = sb + OFF_B + ((y - 1 + i + 400) % NSLOT) * B_PLANE;

#pragma unroll
        for (int kc = 0; kc < 4; kc++) {
#pragma unroll
            for (int dx = 0; dx < 3; dx++) {
                const int pxm = nb + dx + b_noff;
                const uint32_t bRow = (uint32_t)(pxm * 128);
                const uint32_t cB =
                    (uint32_t)((((kc << 1) | b_kh) ^ (pxm & 7)) << 4);
                // B n8 fragments for all 10 planes (10 LDSM.x2)
                uint32_t BF[NSLOT][2];
#pragma unroll
                for (int pl = 0; pl < NSLOT; pl++)
                    ldmx2(BF[pl][0], BF[pl][1], plH[pl] + bRow + cB);
                const uint32_t cA = (uint32_t)((((kc << 1) | a_kh) ^ r7) << 4);
#pragma unroll
                for (int dy = 0; dy < 3; dy++) {
                    const int t = dy * 3 + dx;
                    const uint32_t aHp = sb + (uint32_t)(t * 32 * 128);
#pragma unroll
                    for (int m = 0; m < 2; m++) {
                        uint32_t AH[4];
                        ldmx4(AH[0], AH[1], AH[2], AH[3],
                              aHp + (uint32_t)((m * 16 + a_row0) * 128) + cA);
                        // row r uses plane (r + dy)
#pragma unroll
                        for (int r = 0; r < RPI; r++)
                            mma16816(acc[r][m], AH, BF[r + dy][0], BF[r + dy][1]);
                    }
                }
            }
        }

        // epilogue (global only, no SMEM)
#pragma unroll
        for (int r = 0; r < RPI; r++) {
            const int yy = y + r;
            int x = x0 + nb + col_d;
#pragma unroll
            for (int m = 0; m < 2; m++) {
                float* c = acc[r][m];
#pragma unroll
                for (int h = 0; h < 2; h++) {
                    int co = co_base + m * 16 + row_d + h * 8;
                    if (co < COUT) {
                        float bv = __ldg(bias + co);
                        float v0 = c[2 * h] + bv, v1 = c[2 * h + 1] + bv;
                        if (RELU) { v0 = fmaxf(v0, 0.f); v1 = fmaxf(v1, 0.f); }
                        size_t idx = (((size_t)b * COUT + co) * HH + yy) * WW + x;
                        if (PACK_OUT) {
                            __half2 hv = __floats2half2_rn(v0, v1);
                            *reinterpret_cast<__half2*>((__half*)outv + idx) = hv;
                        } else {
                            *reinterpret_cast<float2*>((float*)outv + idx) =
                                make_float2(v0, v1);
                        }
                    }
                }
            }
        }

        if (y + RPI < yend) {
            __syncthreads();
#pragma unroll 1
            for (int i = 9; i <= 16; i++) stage_B(y + i);
            __syncthreads();
        }
    }
}

// ======================= scalar conv1 (4 -> 64) =============================
__device__ __forceinline__ unsigned long long pack2(float x, float y) {
    unsigned long long r;
    asm("mov.b64 %0, {%1, %2};" : "=l"(r) : "f"(x), "f"(y));
    return r;
}
__device__ __forceinline__ unsigned long long bcast2(float x) { return pack2(x, x); }
__device__ __forceinline__ float2 unpack2(unsigned long long v) {
    float2 f;
    asm("mov.b64 {%0, %1}, %2;" : "=f"(f.x), "=f"(f.y) : "l"(v));
    return f;
}
__device__ __forceinline__ unsigned long long ffma2(unsigned long long a,
                                                    unsigned long long b,
                                                    unsigned long long c) {
    unsigned long long d;
    asm("fma.rn.f32x2 %0, %1, %2, %3;" : "=l"(d) : "l"(a), "l"(b), "l"(c));
    return d;
}

__global__ __launch_bounds__(512, 1)
void conv1_kernel(const float* __restrict__ rgb, const float* __restrict__ depth,
                  const float* __restrict__ wgt, const float* __restrict__ bias,
                  __half* __restrict__ out) {
    constexpr int QS = 16, PIX = 4, CCH = 4;
    constexpr int NP = 8, NP2 = 4;
    __shared__ __align__(16) float ws[CCH][9][4][QS];

    const int tid = threadIdx.x;
    const int lx = tid & 31;
    const int ty = (tid >> 5) & 3;
    const int q = tid >> 7;
    const int x = blockIdx.x * 32 + lx;
    const int y0 = blockIdx.y * (4 * PIX) + ty * PIX;
    const int b = blockIdx.z;
    const int co0 = q * QS;

    unsigned long long acc[PIX][NP];
#pragma unroll
    for (int pr = 0; pr < NP; pr++) {
        unsigned long long bb = pack2(__ldg(bias + co0 + 2 * pr),
                                      __ldg(bias + co0 + 2 * pr + 1));
#pragma unroll
        for (int p = 0; p < PIX; p++) acc[p][pr] = bb;
    }

    int rowoff[PIX + 2];
    bool rok[PIX + 2];
#pragma unroll
    for (int r = 0; r < PIX + 2; r++) {
        int yy = y0 - 1 + r;
        rok[r] = (yy >= 0) && (yy < HH);
        rowoff[r] = yy * WW;
    }
    const bool xok0 = (x > 0), xok2 = (x < WW - 1);

    for (int i = tid; i < CCH * 9 * 4 * QS; i += 512) {
        int col = i % QS;
        int qq = (i / QS) % 4;
        int t = (i / (QS * 4)) % 9;
        int cl = i / (QS * 4 * 9);
        (&ws[0][0][0][0])[i] = __ldg(wgt + ((size_t)(qq * QS + col) * 4 + cl) * 9 + t);
    }
    __syncthreads();

#pragma unroll
    for (int ci = 0; ci < 4; ci++) {
        const float* ip = (ci < 3) ? (rgb + ((size_t)b * 3 + ci) * HWSZ)
                                   : (depth + (size_t)b * HWSZ);
        const float* ipx = ip + x;
        float v[PIX + 2][3];
#pragma unroll
        for (int r = 0; r < PIX + 2; r++) {
            v[r][0] = (rok[r] && xok0) ? __ldg(ipx + rowoff[r] - 1) : 0.f;
            v[r][1] = rok[r] ? __ldg(ipx + rowoff[r]) : 0.f;
            v[r][2] = (rok[r] && xok2) ? __ldg(ipx + rowoff[r] + 1) : 0.f;
        }
#pragma unroll
        for (int dy = 0; dy < 3; dy++) {
#pragma unroll
            for (int dx = 0; dx < 3; dx++) {
                const ulonglong2* wp =
                    reinterpret_cast<const ulonglong2*>(&ws[ci][dy * 3 + dx][q][0]);
                ulonglong2 wq[NP2];
#pragma unroll
                for (int j = 0; j < NP2; j++) wq[j] = wp[j];
#pragma unroll
                for (int p = 0; p < PIX; p++) {
                    unsigned long long vv = bcast2(v[p + dy][dx]);
#pragma unroll
                    for (int j = 0; j < NP2; j++) {
                        acc[p][2 * j] = ffma2(vv, wq[j].x, acc[p][2 * j]);
                        acc[p][2 * j + 1] = ffma2(vv, wq[j].y, acc[p][2 * j + 1]);
                    }
                }
            }
        }
    }

#pragma unroll
    for (int p = 0; p < PIX; p++) {
        size_t base = ((size_t)b * 64) * HWSZ + (size_t)(y0 + p) * WW + x;
#pragma unroll
        for (int pr = 0; pr < NP; pr++) {
            float2 f = unpack2(acc[p][pr]);
            f.x = fmaxf(f.x, 0.f);
            f.y = fmaxf(f.y, 0.f);
            int co = co0 + 2 * pr;
            out[base + (size_t)co * HWSZ] = __float2half_rn(f.x);
            out[base + (size_t)(co + 1) * HWSZ] = __float2half_rn(f.y);
        }
    }
}

// ======================= softmax + bokeh ====================================
__global__ __launch_bounds__(128, 4)
void softmax_bokeh_kernel(const float* __restrict__ logits,
                          const float* __restrict__ rgb,
                          float* __restrict__ out) {
    __shared__ float tile[3][12][40];
    const int tid = threadIdx.x;
    const int lx = tid & 31;
    const int ty = tid >> 5;
    const int x = blockIdx.x * 32 + lx;
    const int y = blockIdx.y * 4 + ty;
    const int b = blockIdx.z;
    const int gx0 = blockIdx.x * 32 - 4;
    const int gy0 = blockIdx.y * 4 - 4;

    for (int i = tid; i < 3 * 12 * 40; i += 128) {
        int xx = i % 40;
        int yy = (i / 40) % 12;
        int c = i / 480;
        int gx = gx0 + xx, gy = gy0 + yy;
        float v = 0.f;
        if (gx >= 0 && gx < WW && gy >= 0 && gy < HH)
            v = rgb[((size_t)b * 3 + c) * HWSZ + (size_t)gy * WW + gx];
        tile[c][yy][xx] = v;
    }
    __syncthreads();

    float lg[81];
    const float* lp = logits + (size_t)b * 81 * HWSZ + (size_t)y * WW + x;
    float m = -1e30f;
#pragma unroll
    for (int t = 0; t < 81; t++) {
        lg[t] = __ldg(lp + (size_t)t * HWSZ);
        m = fmaxf(m, lg[t]);
    }
    float s = 0.f;
#pragma unroll
    for (int t = 0; t < 81; t++) {
        float e = __expf(lg[t] - m);
        lg[t] = e;
        s += e;
    }
    float inv = 1.f / s;

    float r = 0.f, g = 0.f, bl = 0.f;
#pragma unroll
    for (int dy = 0; dy < 9; dy++) {
#pragma unroll
        for (int dx = 0; dx < 9; dx++) {
            float f = lg[dy * 9 + dx] * inv;
            r += f * tile[0][ty + dy][lx + dx];
            g += f * tile[1][ty + dy][lx + dx];
            bl += f * tile[2][ty + dy][lx + dx];
        }
    }
    size_t ob = (size_t)b * 3 * HWSZ + (size_t)y * WW + x;
    out[ob] = r;
    out[ob + HWSZ] = g;
    out[ob + 2 * HWSZ] = bl;
}

// ======================= launch =============================================
extern "C" void kernel_launch(void* const* d_in, const int* in_sizes, int n_in,
                              void* d_out, int out_size) {
    const float* rgb   = (const float*)d_in[0];
    const float* depth = (const float*)d_in[1];
    const float* w1    = (const float*)d_in[2];
    const float* b1    = (const float*)d_in[3];
    const float* w2    = (const float*)d_in[4];
    const float* b2    = (const float*)d_in[5];
    const float* w3    = (const float*)d_in[6];
    const float* b3    = (const float*)d_in[7];
    float* out = (float*)d_out;

    __half *h1, *h2;
    float* lg;
    cudaGetSymbolAddress((void**)&h1, g_h1);
    cudaGetSymbolAddress((void**)&h2, g_h2);
    cudaGetSymbolAddress((void**)&lg, g_logits);

    cudaFuncSetAttribute(conv3x3_hmma<64, 2, true, true>,
                         cudaFuncAttributeMaxDynamicSharedMemorySize, HMMA_SMEM);
    cudaFuncSetAttribute(conv3x3_hmma<81, 3, false, false>,
                         cudaFuncAttributeMaxDynamicSharedMemorySize, HMMA_SMEM);

    // conv1: scalar FFMA2, writes fp16 h1
    conv1_kernel<<<dim3(WW / 32, HH / 16, BATCH), 512>>>(rgb, depth, w1, b1, h1);
    // conv2: HMMA implicit GEMM (2 co-slices of 32), fp16 in / fp16 out
    conv3x3_hmma<64, 2, true, true><<<dim3(WW / NPX, HH / RPC, 2 * BATCH),
                                      NTHREADS, HMMA_SMEM>>>(h1, w2, b2, h2);
    // conv3: HMMA implicit GEMM (3 co-slices of 32, 81 real), fp16 in / f32 out
    conv3x3_hmma<81, 3, false, false><<<dim3(WW / NPX, HH / RPC, 3 * BATCH),
                                        NTHREADS, HMMA_SMEM>>>(h2, w3, b3, lg);
    // softmax + bokeh
    softmax_bokeh_kernel<<<dim3(WW / 32, HH / 4, BATCH), 128>>>(lg, rgb, out);
}

// round 15
// speedup vs baseline: 1.1647x; 1.1647x over previous
#include <cuda_runtime.h>
#include <cuda_fp16.h>
#include <cstdint>
#include <cstddef>

#define HH 384
#define WW 384
#define BATCH 4
#define HWSZ (HH * WW)

// h1/h2: plain fp16 activations, layout [b][c][y][x]
__device__ __half g_h1[(size_t)BATCH * 64 * HWSZ];
__device__ __half g_h2[(size_t)BATCH * 64 * HWSZ];
__device__ float  g_logits[(size_t)BATCH * 81 * HWSZ];

// =============================== helpers ====================================
__device__ __forceinline__ uint32_t smem_u32(const void* p) {
    uint32_t a;
    asm("{ .reg .u64 t; cvta.to.shared.u64 t, %1; cvt.u32.u64 %0, t; }"
        : "=r"(a) : "l"(p));
    return a;
}
__device__ __forceinline__ void ldmx4(uint32_t& r0, uint32_t& r1, uint32_t& r2,
                                      uint32_t& r3, uint32_t addr) {
    asm volatile("ldmatrix.sync.aligned.m8n8.x4.shared.b16 {%0,%1,%2,%3}, [%4];"
                 : "=r"(r0), "=r"(r1), "=r"(r2), "=r"(r3) : "r"(addr));
}
__device__ __forceinline__ void ldmx2(uint32_t& r0, uint32_t& r1, uint32_t addr) {
    asm volatile("ldmatrix.sync.aligned.m8n8.x2.shared.b16 {%0,%1}, [%2];"
                 : "=r"(r0), "=r"(r1) : "r"(addr));
}
__device__ __forceinline__ void mma16816(float* c, const uint32_t* a,
                                         uint32_t b0, uint32_t b1) {
    asm volatile(
        "mma.sync.aligned.m16n8k16.row.col.f32.f16.f16.f32 "
        "{%0,%1,%2,%3}, {%4,%5,%6,%7}, {%8,%9}, {%0,%1,%2,%3};"
        : "+f"(c[0]), "+f"(c[1]), "+f"(c[2]), "+f"(c[3])
        : "r"(a[0]), "r"(a[1]), "r"(a[2]), "r"(a[3]), "r"(b0), "r"(b1));
}
__device__ __forceinline__ uint32_t packh2(float f0, float f1) {
    uint32_t h;
    asm("cvt.rn.f16x2.f32 %0, %1, %2;" : "=r"(h) : "f"(f1), "f"(f0));
    return h;
}

// ===================== HMMA implicit-GEMM 3x3 conv ==========================
// Single-fp16 products. Per CTA: co-slice M=32, px-tile N=128, RPC=32 rows,
// 4 rows per mainloop iteration over a 10-plane SMEM ring.
// 1024 threads / 32 warps: warp = (wy 0..1: co-half of 16) x (wx 0..15: 8-px).
// Single-barrier pipeline: iteration k reads planes y-1..y+4 and stages
// y+5..y+8 (slot-disjoint mod 10 from reads of iterations k and k+1), so one
// __syncthreads per iteration suffices; staging LDGs overlap MMA tails.
#define RPC 32
#define RPI 4
#define NPX 128
#define A_PLANE (9 * 32 * 128)             // 36864 (fp16 weights)
#define OFF_B   A_PLANE
#define B_PLANE (132 * 128)                // 16896 per slot
#define NSLOT 10
#define HMMA_SMEM (OFF_B + NSLOT * B_PLANE)  // 205824
#define NTHREADS 1024
#define NWARPS 32

template <int COUT, int NSLICE, bool RELU, bool PACK_OUT>
__global__ __launch_bounds__(NTHREADS, 1)
void conv3x3_hmma(const __half* __restrict__ in, const float* __restrict__ wgt,
                  const float* __restrict__ bias, void* __restrict__ outv) {
    extern __shared__ __align__(128) char smem[];
    const uint32_t sb = smem_u32(smem);
    const int tid = threadIdx.x, warp = tid >> 5, lane = tid & 31;
    const int x0 = blockIdx.x * NPX;
    const int y0 = blockIdx.y * RPC;
    const int mslice = blockIdx.z % NSLICE;
    const int b = blockIdx.z / NSLICE;
    const int co_base = mslice * 32;
    const int wy = warp & 1;      // co half (16)
    const int wx = warp >> 1;     // px slice (8)

    // ---- stage A: 9 taps x 32 co x 64 ci fp16, swizzled [co][ci] ----
    {
        const int cpl = lane & 3, po = lane >> 2;
        for (int it = warp; it < 288; it += NWARPS) {
            int t = it / 32, r = it & 31;
            int cotile = r >> 3, c = r & 7;
            int co = cotile * 8 + po;
            int ci0 = c * 8 + cpl * 2;
            int cog = co_base + co;
            float f0 = 0.f, f1 = 0.f;
            if (cog < COUT) {
                const float* wp = wgt + ((size_t)cog * 64 + ci0) * 9 + t;
                f0 = __ldg(wp);
                f1 = __ldg(wp + 9);
            }
            uint32_t h = packh2(f0, f1);
            uint32_t off = (uint32_t)((t * 32 + co) * 128 +
                                      ((c ^ (co & 7)) << 4) + cpl * 4);
            asm volatile("st.shared.b32 [%0], %1;" :: "r"(sb + off), "r"(h) : "memory");
        }
    }

    // ---- B row-plane stage: plane row yy -> slot (yy+400)%NSLOT ----
    auto stage_B = [&](int yy) {
        const int slot = (yy + 400) % NSLOT;
        const bool ok_row = (yy >= 0) && (yy < HH);
        const unsigned short* src = reinterpret_cast<const unsigned short*>(
            in + ((size_t)b * 64 * HH + (ok_row ? yy : 0)) * WW);
        const int cpl = lane & 3, po = lane >> 2;
        const uint32_t bH = sb + OFF_B + slot * B_PLANE;
        for (int it = warp; it < 136; it += NWARPS) {
            int c = it & 7, pxt = it >> 3;
            int px = pxt * 8 + po;
            if (px >= 132) continue;
            int ci0 = c * 8 + cpl * 2;
            int gx = x0 - 1 + px;
            bool ok = ok_row && (gx >= 0) && (gx < WW);
            const unsigned short* p = src + (size_t)ci0 * HWSZ + (ok ? gx : 0);
            uint32_t s0 = ok ? (uint32_t)__ldg(p) : 0u;
            uint32_t s1 = ok ? (uint32_t)__ldg(p + HWSZ) : 0u;
            uint32_t hi = s0 | (s1 << 16);
            uint32_t off = (uint32_t)(px * 128 + ((c ^ (px & 7)) << 4) + cpl * 4);
            asm volatile("st.shared.b32 [%0], %1;" :: "r"(bH + off), "r"(hi) : "memory");
        }
    };

    // initial fill: planes y0-1 .. y0+4
    for (int i = -1; i <= 4; i++) stage_B(y0 + i);
    __syncthreads();

    const int r7 = lane & 7, g = lane >> 3;
    const int a_row = wy * 16 + r7 + ((g & 1) << 3);  // co row within 32
    const int a_kh = g >> 1;
    const int b_noff = r7;
    const int b_kh = g & 1;
    const int nb = wx * 8;
    const int row_d = lane >> 2, col_d = (lane & 3) * 2;

    const int yend = y0 + RPC;
#pragma unroll 1
    for (int y = y0; y < yend; y += RPI) {
        float acc[RPI][4];
#pragma unroll
        for (int r = 0; r < RPI; r++)
#pragma unroll
            for (int j = 0; j < 4; j++) acc[r][j] = 0.f;

        // plane slots: index i = input row (y-1+i), i=0..5
        uint32_t plH[6];
#pragma unroll
        for (int i = 0; i < 6; i++)
            plH[i] = sb + OFF_B + ((y - 1 + i + 400) % NSLOT) * B_PLANE;

#pragma unroll
        for (int kc = 0; kc < 4; kc++) {
#pragma unroll
            for (int dx = 0; dx < 3; dx++) {
                const int pxm = nb + dx + b_noff;
                const uint32_t bRow = (uint32_t)(pxm * 128);
                const uint32_t cB =
                    (uint32_t)((((kc << 1) | b_kh) ^ (pxm & 7)) << 4);
                // B n8 fragments for the 6 live planes (6 LDSM.x2)
                uint32_t BF[6][2];
#pragma unroll
                for (int pl = 0; pl < 6; pl++)
                    ldmx2(BF[pl][0], BF[pl][1], plH[pl] + bRow + cB);
                const uint32_t cA = (uint32_t)((((kc << 1) | a_kh) ^ r7) << 4);
#pragma unroll
                for (int dy = 0; dy < 3; dy++) {
                    const int t = dy * 3 + dx;
                    const uint32_t aHp = sb + (uint32_t)(t * 32 * 128);
                    uint32_t AH[4];
                    ldmx4(AH[0], AH[1], AH[2], AH[3],
                          aHp + (uint32_t)(a_row * 128) + cA);
                    // row r uses plane (r + dy)
#pragma unroll
                    for (int r = 0; r < RPI; r++)
                        mma16816(acc[r], AH, BF[r + dy][0], BF[r + dy][1]);
                }
            }
        }

        // stage next 4 planes (slots disjoint from all concurrent reads);
        // LDGs overlap other warps' mainloop tails. Single sync below.
        if (y + RPI < yend) {
            stage_B(y + 5);
            stage_B(y + 6);
            stage_B(y + 7);
            stage_B(y + 8);
        }
        __syncthreads();

        // epilogue (global only, no SMEM)
#pragma unroll
        for (int r = 0; r < RPI; r++) {
            const int yy = y + r;
            float* c = acc[r];
            int x = x0 + nb + col_d;
#pragma unroll
            for (int h = 0; h < 2; h++) {
                int co = co_base + wy * 16 + row_d + h * 8;
                if (co < COUT) {
                    float bv = __ldg(bias + co);
                    float v0 = c[2 * h] + bv, v1 = c[2 * h + 1] + bv;
                    if (RELU) { v0 = fmaxf(v0, 0.f); v1 = fmaxf(v1, 0.f); }
                    size_t idx = (((size_t)b * COUT + co) * HH + yy) * WW + x;
                    if (PACK_OUT) {
                        __half2 hv = __floats2half2_rn(v0, v1);
                        *reinterpret_cast<__half2*>((__half*)outv + idx) = hv;
                    } else {
                        *reinterpret_cast<float2*>((float*)outv + idx) =
                            make_float2(v0, v1);
                    }
                }
            }
        }
    }
}

// ======================= scalar conv1 (4 -> 64) =============================
__device__ __forceinline__ unsigned long long pack2(float x, float y) {
    unsigned long long r;
    asm("mov.b64 %0, {%1, %2};" : "=l"(r) : "f"(x), "f"(y));
    return r;
}
__device__ __forceinline__ unsigned long long bcast2(float x) { return pack2(x, x); }
__device__ __forceinline__ float2 unpack2(unsigned long long v) {
    float2 f;
    asm("mov.b64 {%0, %1}, %2;" : "=f"(f.x), "=f"(f.y) : "l"(v));
    return f;
}
__device__ __forceinline__ unsigned long long ffma2(unsigned long long a,
                                                    unsigned long long b,
                                                    unsigned long long c) {
    unsigned long long d;
    asm("fma.rn.f32x2 %0, %1, %2, %3;" : "=l"(d) : "l"(a), "l"(b), "l"(c));
    return d;
}

__global__ __launch_bounds__(512, 1)
void conv1_kernel(const float* __restrict__ rgb, const float* __restrict__ depth,
                  const float* __restrict__ wgt, const float* __restrict__ bias,
                  __half* __restrict__ out) {
    constexpr int QS = 16, PIX = 4, CCH = 4;
    constexpr int NP = 8, NP2 = 4;
    __shared__ __align__(16) float ws[CCH][9][4][QS];

    const int tid = threadIdx.x;
    const int lx = tid & 31;
    const int ty = (tid >> 5) & 3;
    const int q = tid >> 7;
    const int x = blockIdx.x * 32 + lx;
    const int y0 = blockIdx.y * (4 * PIX) + ty * PIX;
    const int b = blockIdx.z;
    const int co0 = q * QS;

    unsigned long long acc[PIX][NP];
#pragma unroll
    for (int pr = 0; pr < NP; pr++) {
        unsigned long long bb = pack2(__ldg(bias + co0 + 2 * pr),
                                      __ldg(bias + co0 + 2 * pr + 1));
#pragma unroll
        for (int p = 0; p < PIX; p++) acc[p][pr] = bb;
    }

    int rowoff[PIX + 2];
    bool rok[PIX + 2];
#pragma unroll
    for (int r = 0; r < PIX + 2; r++) {
        int yy = y0 - 1 + r;
        rok[r] = (yy >= 0) && (yy < HH);
        rowoff[r] = yy * WW;
    }
    const bool xok0 = (x > 0), xok2 = (x < WW - 1);

    for (int i = tid; i < CCH * 9 * 4 * QS; i += 512) {
        int col = i % QS;
        int qq = (i / QS) % 4;
        int t = (i / (QS * 4)) % 9;
        int cl = i / (QS * 4 * 9);
        (&ws[0][0][0][0])[i] = __ldg(wgt + ((size_t)(qq * QS + col) * 4 + cl) * 9 + t);
    }
    __syncthreads();

#pragma unroll
    for (int ci = 0; ci < 4; ci++) {
        const float* ip = (ci < 3) ? (rgb + ((size_t)b * 3 + ci) * HWSZ)
                                   : (depth + (size_t)b * HWSZ);
        const float* ipx = ip + x;
        float v[PIX + 2][3];
#pragma unroll
        for (int r = 0; r < PIX + 2; r++) {
            v[r][0] = (rok[r] && xok0) ? __ldg(ipx + rowoff[r] - 1) : 0.f;
            v[r][1] = rok[r] ? __ldg(ipx + rowoff[r]) : 0.f;
            v[r][2] = (rok[r] && xok2) ? __ldg(ipx + rowoff[r] + 1) : 0.f;
        }
#pragma unroll
        for (int dy = 0; dy < 3; dy++) {
#pragma unroll
            for (int dx = 0; dx < 3; dx++) {
                const ulonglong2* wp =
                    reinterpret_cast<const ulonglong2*>(&ws[ci][dy * 3 + dx][q][0]);
                ulonglong2 wq[NP2];
#pragma unroll
                for (int j = 0; j < NP2; j++) wq[j] = wp[j];
#pragma unroll
                for (int p = 0; p < PIX; p++) {
                    unsigned long long vv = bcast2(v[p + dy][dx]);
#pragma unroll
                    for (int j = 0; j < NP2; j++) {
                        acc[p][2 * j] = ffma2(vv, wq[j].x, acc[p][2 * j]);
                        acc[p][2 * j + 1] = ffma2(vv, wq[j].y, acc[p][2 * j + 1]);
                    }
                }
            }
        }
    }

#pragma unroll
    for (int p = 0; p < PIX; p++) {
        size_t base = ((size_t)b * 64) * HWSZ + (size_t)(y0 + p) * WW + x;
#pragma unroll
        for (int pr = 0; pr < NP; pr++) {
            float2 f = unpack2(acc[p][pr]);
            f.x = fmaxf(f.x, 0.f);
            f.y = fmaxf(f.y, 0.f);
            int co = co0 + 2 * pr;
            out[base + (size_t)co * HWSZ] = __float2half_rn(f.x);
            out[base + (size_t)(co + 1) * HWSZ] = __float2half_rn(f.y);
        }
    }
}

// ======================= softmax + bokeh ====================================
__global__ __launch_bounds__(128, 4)
void softmax_bokeh_kernel(const float* __restrict__ logits,
                          const float* __restrict__ rgb,
                          float* __restrict__ out) {
    __shared__ float tile[3][12][40];
    const int tid = threadIdx.x;
    const int lx = tid & 31;
    const int ty = tid >> 5;
    const int x = blockIdx.x * 32 + lx;
    const int y = blockIdx.y * 4 + ty;
    const int b = blockIdx.z;
    const int gx0 = blockIdx.x * 32 - 4;
    const int gy0 = blockIdx.y * 4 - 4;

    for (int i = tid; i < 3 * 12 * 40; i += 128) {
        int xx = i % 40;
        int yy = (i / 40) % 12;
        int c = i / 480;
        int gx = gx0 + xx, gy = gy0 + yy;
        float v = 0.f;
        if (gx >= 0 && gx < WW && gy >= 0 && gy < HH)
            v = rgb[((size_t)b * 3 + c) * HWSZ + (size_t)gy * WW + gx];
        tile[c][yy][xx] = v;
    }
    __syncthreads();

    float lg[81];
    const float* lp = logits + (size_t)b * 81 * HWSZ + (size_t)y * WW + x;
    float m = -1e30f;
#pragma unroll
    for (int t = 0; t < 81; t++) {
        lg[t] = __ldg(lp + (size_t)t * HWSZ);
        m = fmaxf(m, lg[t]);
    }
    float s = 0.f;
#pragma unroll
    for (int t = 0; t < 81; t++) {
        float e = __expf(lg[t] - m);
        lg[t] = e;
        s += e;
    }
    float inv = 1.f / s;

    float r = 0.f, g = 0.f, bl = 0.f;
#pragma unroll
    for (int dy = 0; dy < 9; dy++) {
#pragma unroll
        for (int dx = 0; dx < 9; dx++) {
            float f = lg[dy * 9 + dx] * inv;
            r += f * tile[0][ty + dy][lx + dx];
            g += f * tile[1][ty + dy][lx + dx];
            bl += f * tile[2][ty + dy][lx + dx];
        }
    }
    size_t ob = (size_t)b * 3 * HWSZ + (size_t)y * WW + x;
    out[ob] = r;
    out[ob + HWSZ] = g;
    out[ob + 2 * HWSZ] = bl;
}

// ======================= launch =============================================
extern "C" void kernel_launch(void* const* d_in, const int* in_sizes, int n_in,
                              void* d_out, int out_size) {
    const float* rgb   = (const float*)d_in[0];
    const float* depth = (const float*)d_in[1];
    const float* w1    = (const float*)d_in[2];
    const float* b1    = (const float*)d_in[3];
    const float* w2    = (const float*)d_in[4];
    const float* b2    = (const float*)d_in[5];
    const float* w3    = (const float*)d_in[6];
    const float* b3    = (const float*)d_in[7];
    float* out = (float*)d_out;

    __half *h1, *h2;
    float* lg;
    cudaGetSymbolAddress((void**)&h1, g_h1);
    cudaGetSymbolAddress((void**)&h2, g_h2);
    cudaGetSymbolAddress((void**)&lg, g_logits);

    cudaFuncSetAttribute(conv3x3_hmma<64, 2, true, true>,
                         cudaFuncAttributeMaxDynamicSharedMemorySize, HMMA_SMEM);
    cudaFuncSetAttribute(conv3x3_hmma<81, 3, false, false>,
                         cudaFuncAttributeMaxDynamicSharedMemorySize, HMMA_SMEM);

    // conv1: scalar FFMA2, writes fp16 h1
    conv1_kernel<<<dim3(WW / 32, HH / 16, BATCH), 512>>>(rgb, depth, w1, b1, h1);
    // conv2: HMMA implicit GEMM (2 co-slices of 32), fp16 in / fp16 out
    conv3x3_hmma<64, 2, true, true><<<dim3(WW / NPX, HH / RPC, 2 * BATCH),
                                      NTHREADS, HMMA_SMEM>>>(h1, w2, b2, h2);
    // conv3: HMMA implicit GEMM (3 co-slices of 32, 81 real), fp16 in / f32 out
    conv3x3_hmma<81, 3, false, false><<<dim3(WW / NPX, HH / RPC, 3 * BATCH),
                                        NTHREADS, HMMA_SMEM>>>(h2, w3, b3, lg);
    // softmax + bokeh
    softmax_bokeh_kernel<<<dim3(WW / 32, HH / 4, BATCH), 128>>>(lg, rgb, out);
}

// round 16
// speedup vs baseline: 1.1814x; 1.0143x over previous
#include <cuda_runtime.h>
#include <cuda_fp16.h>
#include <cstdint>
#include <cstddef>

#define HH 384
#define WW 384
#define BATCH 4
#define HWSZ (HH * WW)

// h1/h2: plain fp16 activations, layout [b][c][y][x]
__device__ __half g_h1[(size_t)BATCH * 64 * HWSZ];
__device__ __half g_h2[(size_t)BATCH * 64 * HWSZ];
__device__ float  g_logits[(size_t)BATCH * 81 * HWSZ];

// =============================== helpers ====================================
__device__ __forceinline__ uint32_t smem_u32(const void* p) {
    uint32_t a;
    asm("{ .reg .u64 t; cvta.to.shared.u64 t, %1; cvt.u32.u64 %0, t; }"
        : "=r"(a) : "l"(p));
    return a;
}
__device__ __forceinline__ void ldmx4(uint32_t& r0, uint32_t& r1, uint32_t& r2,
                                      uint32_t& r3, uint32_t addr) {
    asm volatile("ldmatrix.sync.aligned.m8n8.x4.shared.b16 {%0,%1,%2,%3}, [%4];"
                 : "=r"(r0), "=r"(r1), "=r"(r2), "=r"(r3) : "r"(addr));
}
__device__ __forceinline__ void mma16816(float* c, const uint32_t* a,
                                         uint32_t b0, uint32_t b1) {
    asm volatile(
        "mma.sync.aligned.m16n8k16.row.col.f32.f16.f16.f32 "
        "{%0,%1,%2,%3}, {%4,%5,%6,%7}, {%8,%9}, {%0,%1,%2,%3};"
        : "+f"(c[0]), "+f"(c[1]), "+f"(c[2]), "+f"(c[3])
        : "r"(a[0]), "r"(a[1]), "r"(a[2]), "r"(a[3]), "r"(b0), "r"(b1));
}
__device__ __forceinline__ uint32_t packh2(float f0, float f1) {
    uint32_t h;
    asm("cvt.rn.f16x2.f32 %0, %1, %2;" : "=r"(h) : "f"(f1), "f"(f0));
    return h;
}

// ===================== HMMA implicit-GEMM 3x3 conv ==========================
// Single-fp16 products. Per CTA: co-slice M=32, px-tile N=128, RPC=32 rows,
// 4 rows per mainloop iteration over a 6-plane SMEM ring (R13 structure).
// 1024 threads / 32 warps: warp = (wy 0..1: co-half of 16) x (wx 0..15: 8-px).
// NEW: B fragments for two planes are fetched with ONE ldmatrix.x4 —
// lanes 0-15 address plane p (kh0/kh1), lanes 16-31 address plane p+1.
#define RPC 32
#define RPI 4
#define NPX 128
#define A_PLANE (9 * 32 * 128)             // 36864 (fp16 weights)
#define OFF_B   A_PLANE
#define B_PLANE (132 * 128)                // 16896 per slot
#define NSLOT 6
#define HMMA_SMEM (OFF_B + NSLOT * B_PLANE)  // 138240
#define NTHREADS 1024
#define NWARPS 32

template <int COUT, int NSLICE, bool RELU, bool PACK_OUT>
__global__ __launch_bounds__(NTHREADS, 1)
void conv3x3_hmma(const __half* __restrict__ in, const float* __restrict__ wgt,
                  const float* __restrict__ bias, void* __restrict__ outv) {
    extern __shared__ __align__(128) char smem[];
    const uint32_t sb = smem_u32(smem);
    const int tid = threadIdx.x, warp = tid >> 5, lane = tid & 31;
    const int x0 = blockIdx.x * NPX;
    const int y0 = blockIdx.y * RPC;
    const int mslice = blockIdx.z % NSLICE;
    const int b = blockIdx.z / NSLICE;
    const int co_base = mslice * 32;
    const int wy = warp & 1;      // co half (16)
    const int wx = warp >> 1;     // px slice (8)

    // ---- stage A: 9 taps x 32 co x 64 ci fp16, swizzled [co][ci] ----
    {
        const int cpl = lane & 3, po = lane >> 2;
        for (int it = warp; it < 288; it += NWARPS) {
            int t = it / 32, r = it & 31;
            int cotile = r >> 3, c = r & 7;
            int co = cotile * 8 + po;
            int ci0 = c * 8 + cpl * 2;
            int cog = co_base + co;
            float f0 = 0.f, f1 = 0.f;
            if (cog < COUT) {
                const float* wp = wgt + ((size_t)cog * 64 + ci0) * 9 + t;
                f0 = __ldg(wp);
                f1 = __ldg(wp + 9);
            }
            uint32_t h = packh2(f0, f1);
            uint32_t off = (uint32_t)((t * 32 + co) * 128 +
                                      ((c ^ (co & 7)) << 4) + cpl * 4);
            asm volatile("st.shared.b32 [%0], %1;" :: "r"(sb + off), "r"(h) : "memory");
        }
    }

    // ---- B row-plane stage: plane row yy -> slot (yy+NSLOT)%NSLOT ----
    auto stage_B = [&](int yy) {
        const int slot = (yy + NSLOT) % NSLOT;
        const bool ok_row = (yy >= 0) && (yy < HH);
        const unsigned short* src = reinterpret_cast<const unsigned short*>(
            in + ((size_t)b * 64 * HH + (ok_row ? yy : 0)) * WW);
        const int cpl = lane & 3, po = lane >> 2;
        const uint32_t bH = sb + OFF_B + slot * B_PLANE;
        for (int it = warp; it < 136; it += NWARPS) {
            int c = it & 7, pxt = it >> 3;
            int px = pxt * 8 + po;
            if (px >= 132) continue;
            int ci0 = c * 8 + cpl * 2;
            int gx = x0 - 1 + px;
            bool ok = ok_row && (gx >= 0) && (gx < WW);
            const unsigned short* p = src + (size_t)ci0 * HWSZ + (ok ? gx : 0);
            uint32_t s0 = ok ? (uint32_t)__ldg(p) : 0u;
            uint32_t s1 = ok ? (uint32_t)__ldg(p + HWSZ) : 0u;
            uint32_t hi = s0 | (s1 << 16);
            uint32_t off = (uint32_t)(px * 128 + ((c ^ (px & 7)) << 4) + cpl * 4);
            asm volatile("st.shared.b32 [%0], %1;" :: "r"(bH + off), "r"(hi) : "memory");
        }
    };

    // initial fill: planes y0-1 .. y0+4
    for (int i = -1; i <= 4; i++) stage_B(y0 + i);
    __syncthreads();

    const int r7 = lane & 7, g = lane >> 3;
    const int a_row = wy * 16 + r7 + ((g & 1) << 3);  // co row within 32
    const int a_kh = g >> 1;
    const int b_kh = g & 1;           // k-half within a plane
    const int pl_sel = (lane >> 4) & 1;  // which plane of an x4 pair
    const int nb = wx * 8;
    const int row_d = lane >> 2, col_d = (lane & 3) * 2;

    const int yend = y0 + RPC;
#pragma unroll 1
    for (int y = y0; y < yend; y += RPI) {
        float acc[RPI][4];
#pragma unroll
        for (int r = 0; r < RPI; r++)
#pragma unroll
            for (int j = 0; j < 4; j++) acc[r][j] = 0.f;

        // plane slots: index i = input row (y-1+i), i=0..5
        uint32_t plH[NSLOT];
#pragma unroll
        for (int i = 0; i < NSLOT; i++)
            plH[i] = sb + OFF_B + ((y - 1 + i + NSLOT * 64) % NSLOT) * B_PLANE;

#pragma unroll
        for (int kc = 0; kc < 4; kc++) {
#pragma unroll
            for (int dx = 0; dx < 3; dx++) {
                const int pxm = nb + dx + r7;
                const uint32_t bRow = (uint32_t)(pxm * 128);
                const uint32_t cB =
                    (uint32_t)((((kc << 1) | b_kh) ^ (pxm & 7)) << 4);
                // B n8 fragments for 6 planes via 3 ldmatrix.x4
                // (lanes 0-15: plane pr, lanes 16-31: plane pr+1)
                uint32_t BF[NSLOT][2];
#pragma unroll
                for (int pr = 0; pr < NSLOT; pr += 2) {
                    uint32_t addr = plH[pr + pl_sel] + bRow + cB;
                    ldmx4(BF[pr][0], BF[pr][1], BF[pr + 1][0], BF[pr + 1][1],
                          addr);
                }
                const uint32_t cA = (uint32_t)((((kc << 1) | a_kh) ^ r7) << 4);
#pragma unroll
                for (int dy = 0; dy < 3; dy++) {
                    const int t = dy * 3 + dx;
                    const uint32_t aHp = sb + (uint32_t)(t * 32 * 128);
                    uint32_t AH[4];
                    ldmx4(AH[0], AH[1], AH[2], AH[3],
                          aHp + (uint32_t)(a_row * 128) + cA);
                    // row r uses plane (r + dy)
#pragma unroll
                    for (int r = 0; r < RPI; r++)
                        mma16816(acc[r], AH, BF[r + dy][0], BF[r + dy][1]);
                }
            }
        }

        // epilogue (global only, no SMEM)
#pragma unroll
        for (int r = 0; r < RPI; r++) {
            const int yy = y + r;
            float* c = acc[r];
            int x = x0 + nb + col_d;
#pragma unroll
            for (int h = 0; h < 2; h++) {
                int co = co_base + wy * 16 + row_d + h * 8;
                if (co < COUT) {
                    float bv = __ldg(bias + co);
                    float v0 = c[2 * h] + bv, v1 = c[2 * h + 1] + bv;
                    if (RELU) { v0 = fmaxf(v0, 0.f); v1 = fmaxf(v1, 0.f); }
                    size_t idx = (((size_t)b * COUT + co) * HH + yy) * WW + x;
                    if (PACK_OUT) {
                        __half2 hv = __floats2half2_rn(v0, v1);
                        *reinterpret_cast<__half2*>((__half*)outv + idx) = hv;
                    } else {
                        *reinterpret_cast<float2*>((float*)outv + idx) =
                            make_float2(v0, v1);
                    }
                }
            }
        }

        if (y + RPI < yend) {
            __syncthreads();
            stage_B(y + 5);
            stage_B(y + 6);
            stage_B(y + 7);
            stage_B(y + 8);
            __syncthreads();
        }
    }
}

// ======================= scalar conv1 (4 -> 64) =============================
__device__ __forceinline__ unsigned long long pack2(float x, float y) {
    unsigned long long r;
    asm("mov.b64 %0, {%1, %2};" : "=l"(r) : "f"(x), "f"(y));
    return r;
}
__device__ __forceinline__ unsigned long long bcast2(float x) { return pack2(x, x); }
__device__ __forceinline__ float2 unpack2(unsigned long long v) {
    float2 f;
    asm("mov.b64 {%0, %1}, %2;" : "=f"(f.x), "=f"(f.y) : "l"(v));
    return f;
}
__device__ __forceinline__ unsigned long long ffma2(unsigned long long a,
                                                    unsigned long long b,
                                                    unsigned long long c) {
    unsigned long long d;
    asm("fma.rn.f32x2 %0, %1, %2, %3;" : "=l"(d) : "l"(a), "l"(b), "l"(c));
    return d;
}

__global__ __launch_bounds__(512, 1)
void conv1_kernel(const float* __restrict__ rgb, const float* __restrict__ depth,
                  const float* __restrict__ wgt, const float* __restrict__ bias,
                  __half* __restrict__ out) {
    constexpr int QS = 16, PIX = 4, CCH = 4;
    constexpr int NP = 8, NP2 = 4;
    __shared__ __align__(16) float ws[CCH][9][4][QS];

    const int tid = threadIdx.x;
    const int lx = tid & 31;
    const int ty = (tid >> 5) & 3;
    const int q = tid >> 7;
    const int x = blockIdx.x * 32 + lx;
    const int y0 = blockIdx.y * (4 * PIX) + ty * PIX;
    const int b = blockIdx.z;
    const int co0 = q * QS;

    unsigned long long acc[PIX][NP];
#pragma unroll
    for (int pr = 0; pr < NP; pr++) {
        unsigned long long bb = pack2(__ldg(bias + co0 + 2 * pr),
                                      __ldg(bias + co0 + 2 * pr + 1));
#pragma unroll
        for (int p = 0; p < PIX; p++) acc[p][pr] = bb;
    }

    int rowoff[PIX + 2];
    bool rok[PIX + 2];
#pragma unroll
    for (int r = 0; r < PIX + 2; r++) {
        int yy = y0 - 1 + r;
        rok[r] = (yy >= 0) && (yy < HH);
        rowoff[r] = yy * WW;
    }
    const bool xok0 = (x > 0), xok2 = (x < WW - 1);

    for (int i = tid; i < CCH * 9 * 4 * QS; i += 512) {
        int col = i % QS;
        int qq = (i / QS) % 4;
        int t = (i / (QS * 4)) % 9;
        int cl = i / (QS * 4 * 9);
        (&ws[0][0][0][0])[i] = __ldg(wgt + ((size_t)(qq * QS + col) * 4 + cl) * 9 + t);
    }
    __syncthreads();

#pragma unroll
    for (int ci = 0; ci < 4; ci++) {
        const float* ip = (ci < 3) ? (rgb + ((size_t)b * 3 + ci) * HWSZ)
                                   : (depth + (size_t)b * HWSZ);
        const float* ipx = ip + x;
        float v[PIX + 2][3];
#pragma unroll
        for (int r = 0; r < PIX + 2; r++) {
            v[r][0] = (rok[r] && xok0) ? __ldg(ipx + rowoff[r] - 1) : 0.f;
            v[r][1] = rok[r] ? __ldg(ipx + rowoff[r]) : 0.f;
            v[r][2] = (rok[r] && xok2) ? __ldg(ipx + rowoff[r] + 1) : 0.f;
        }
#pragma unroll
        for (int dy = 0; dy < 3; dy++) {
#pragma unroll
            for (int dx = 0; dx < 3; dx++) {
                const ulonglong2* wp =
                    reinterpret_cast<const ulonglong2*>(&ws[ci][dy * 3 + dx][q][0]);
                ulonglong2 wq[NP2];
#pragma unroll
                for (int j = 0; j < NP2; j++) wq[j] = wp[j];
#pragma unroll
                for (int p = 0; p < PIX; p++) {
                    unsigned long long vv = bcast2(v[p + dy][dx]);
#pragma unroll
                    for (int j = 0; j < NP2; j++) {
                        acc[p][2 * j] = ffma2(vv, wq[j].x, acc[p][2 * j]);
                        acc[p][2 * j + 1] = ffma2(vv, wq[j].y, acc[p][2 * j + 1]);
                    }
                }
            }
        }
    }

#pragma unroll
    for (int p = 0; p < PIX; p++) {
        size_t base = ((size_t)b * 64) * HWSZ + (size_t)(y0 + p) * WW + x;
#pragma unroll
        for (int pr = 0; pr < NP; pr++) {
            float2 f = unpack2(acc[p][pr]);
            f.x = fmaxf(f.x, 0.f);
            f.y = fmaxf(f.y, 0.f);
            int co = co0 + 2 * pr;
            out[base + (size_t)co * HWSZ] = __float2half_rn(f.x);
            out[base + (size_t)(co + 1) * HWSZ] = __float2half_rn(f.y);
        }
    }
}

// ======================= softmax + bokeh ====================================
__global__ __launch_bounds__(128, 4)
void softmax_bokeh_kernel(const float* __restrict__ logits,
                          const float* __restrict__ rgb,
                          float* __restrict__ out) {
    __shared__ float tile[3][12][40];
    const int tid = threadIdx.x;
    const int lx = tid & 31;
    const int ty = tid >> 5;
    const int x = blockIdx.x * 32 + lx;
    const int y = blockIdx.y * 4 + ty;
    const int b = blockIdx.z;
    const int gx0 = blockIdx.x * 32 - 4;
    const int gy0 = blockIdx.y * 4 - 4;

    for (int i = tid; i < 3 * 12 * 40; i += 128) {
        int xx = i % 40;
        int yy = (i / 40) % 12;
        int c = i / 480;
        int gx = gx0 + xx, gy = gy0 + yy;
        float v = 0.f;
        if (gx >= 0 && gx < WW && gy >= 0 && gy < HH)
            v = rgb[((size_t)b * 3 + c) * HWSZ + (size_t)gy * WW + gx];
        tile[c][yy][xx] = v;
    }
    __syncthreads();

    float lg[81];
    const float* lp = logits + (size_t)b * 81 * HWSZ + (size_t)y * WW + x;
    float m = -1e30f;
#pragma unroll
    for (int t = 0; t < 81; t++) {
        lg[t] = __ldg(lp + (size_t)t * HWSZ);
        m = fmaxf(m, lg[t]);
    }
    float s = 0.f;
#pragma unroll
    for (int t = 0; t < 81; t++) {
        float e = __expf(lg[t] - m);
        lg[t] = e;
        s += e;
    }
    float inv = 1.f / s;

    float r = 0.f, g = 0.f, bl = 0.f;
#pragma unroll
    for (int dy = 0; dy < 9; dy++) {
#pragma unroll
        for (int dx = 0; dx < 9; dx++) {
            float f = lg[dy * 9 + dx] * inv;
            r += f * tile[0][ty + dy][lx + dx];
            g += f * tile[1][ty + dy][lx + dx];
            bl += f * tile[2][ty + dy][lx + dx];
        }
    }
    size_t ob = (size_t)b * 3 * HWSZ + (size_t)y * WW + x;
    out[ob] = r;
    out[ob + HWSZ] = g;
    out[ob + 2 * HWSZ] = bl;
}

// ======================= launch =============================================
extern "C" void kernel_launch(void* const* d_in, const int* in_sizes, int n_in,
                              void* d_out, int out_size) {
    const float* rgb   = (const float*)d_in[0];
    const float* depth = (const float*)d_in[1];
    const float* w1    = (const float*)d_in[2];
    const float* b1    = (const float*)d_in[3];
    const float* w2    = (const float*)d_in[4];
    const float* b2    = (const float*)d_in[5];
    const float* w3    = (const float*)d_in[6];
    const float* b3    = (const float*)d_in[7];
    float* out = (float*)d_out;

    __half *h1, *h2;
    float* lg;
    cudaGetSymbolAddress((void**)&h1, g_h1);
    cudaGetSymbolAddress((void**)&h2, g_h2);
    cudaGetSymbolAddress((void**)&lg, g_logits);

    cudaFuncSetAttribute(conv3x3_hmma<64, 2, true, true>,
                         cudaFuncAttributeMaxDynamicSharedMemorySize, HMMA_SMEM);
    cudaFuncSetAttribute(conv3x3_hmma<81, 3, false, false>,
                         cudaFuncAttributeMaxDynamicSharedMemorySize, HMMA_SMEM);

    // conv1: scalar FFMA2, writes fp16 h1
    conv1_kernel<<<dim3(WW / 32, HH / 16, BATCH), 512>>>(rgb, depth, w1, b1, h1);
    // conv2: HMMA implicit GEMM (2 co-slices of 32), fp16 in / fp16 out
    conv3x3_hmma<64, 2, true, true><<<dim3(WW / NPX, HH / RPC, 2 * BATCH),
                                      NTHREADS, HMMA_SMEM>>>(h1, w2, b2, h2);
    // conv3: HMMA implicit GEMM (3 co-slices of 32, 81 real), fp16 in / f32 out
    conv3x3_hmma<81, 3, false, false><<<dim3(WW / NPX, HH / RPC, 3 * BATCH),
                                        NTHREADS, HMMA_SMEM>>>(h2, w3, b3, lg);
    // softmax + bokeh
    softmax_bokeh_kernel<<<dim3(WW / 32, HH / 4, BATCH), 128>>>(lg, rgb, out);
}

// round 17
// speedup vs baseline: 1.4858x; 1.2576x over previous
#include <cuda_runtime.h>
#include <cuda_fp16.h>
#include <cstdint>
#include <cstddef>

#define HH 384
#define WW 384
#define BATCH 4
#define HWSZ (HH * WW)

// h1/h2: plain fp16 activations, layout [b][c][y][x]
__device__ __half g_h1[(size_t)BATCH * 64 * HWSZ];
__device__ __half g_h2[(size_t)BATCH * 64 * HWSZ];
__device__ float  g_logits[(size_t)BATCH * 81 * HWSZ];

// =============================== helpers ====================================
__device__ __forceinline__ uint32_t smem_u32(const void* p) {
    uint32_t a;
    asm("{ .reg .u64 t; cvta.to.shared.u64 t, %1; cvt.u32.u64 %0, t; }"
        : "=r"(a) : "l"(p));
    return a;
}
__device__ __forceinline__ void ldmx4(uint32_t& r0, uint32_t& r1, uint32_t& r2,
                                      uint32_t& r3, uint32_t addr) {
    asm volatile("ldmatrix.sync.aligned.m8n8.x4.shared.b16 {%0,%1,%2,%3}, [%4];"
                 : "=r"(r0), "=r"(r1), "=r"(r2), "=r"(r3) : "r"(addr));
}
__device__ __forceinline__ void ldmx2(uint32_t& r0, uint32_t& r1, uint32_t addr) {
    asm volatile("ldmatrix.sync.aligned.m8n8.x2.shared.b16 {%0,%1}, [%2];"
                 : "=r"(r0), "=r"(r1) : "r"(addr));
}
__device__ __forceinline__ void mma16816(float* c, const uint32_t* a,
                                         uint32_t b0, uint32_t b1) {
    asm volatile(
        "mma.sync.aligned.m16n8k16.row.col.f32.f16.f16.f32 "
        "{%0,%1,%2,%3}, {%4,%5,%6,%7}, {%8,%9}, {%0,%1,%2,%3};"
        : "+f"(c[0]), "+f"(c[1]), "+f"(c[2]), "+f"(c[3])
        : "r"(a[0]), "r"(a[1]), "r"(a[2]), "r"(a[3]), "r"(b0), "r"(b1));
}
__device__ __forceinline__ uint32_t packh2(float f0, float f1) {
    uint32_t h;
    asm("cvt.rn.f16x2.f32 %0, %1, %2;" : "=r"(h) : "f"(f1), "f"(f0));
    return h;
}

// ===================== HMMA implicit-GEMM 3x3 conv ==========================
// Single-fp16 products. One CTA per (x-tile, y-tile, batch) holds ALL NSLICE
// 32-channel weight slices in SMEM and runs the slice mainloops serially per
// 4-row window — input planes staged ONCE per CTA (was once per slice-CTA).
// px-tile N=128, RPC=32 rows, RPI=4 rows/iter, 6-plane ring (R13 structure).
// 1024 threads / 32 warps: warp = (wy 0..1: co-half of 16) x (wx 0..15: 8-px).
#define RPC 32
#define RPI 4
#define NPX 128
#define A_PLANE (9 * 32 * 128)             // 36864 per slice (fp16 weights)
#define B_PLANE (132 * 128)                // 16896 per slot
#define NSLOT 6
#define NTHREADS 1024
#define NWARPS 32

template <int COUT, int NSLICE, bool RELU, bool PACK_OUT>
__global__ __launch_bounds__(NTHREADS, 1)
void conv3x3_hmma(const __half* __restrict__ in, const float* __restrict__ wgt,
                  const float* __restrict__ bias, void* __restrict__ outv) {
    extern __shared__ __align__(128) char smem[];
    const uint32_t sb = smem_u32(smem);
    const uint32_t OFFB = NSLICE * A_PLANE;
    const int tid = threadIdx.x, warp = tid >> 5, lane = tid & 31;
    const int x0 = blockIdx.x * NPX;
    const int y0 = blockIdx.y * RPC;
    const int b = blockIdx.z;
    const int wy = warp & 1;      // co half (16)
    const int wx = warp >> 1;     // px slice (8)

    // ---- stage A: NSLICE slices x 9 taps x 32 co x 64 ci fp16, swizzled ----
    {
        const int cpl = lane & 3, po = lane >> 2;
        for (int it = warp; it < 288 * NSLICE; it += NWARPS) {
            int ms = it / 288;
            int i2 = it % 288;
            int t = i2 / 32, r = i2 & 31;
            int cotile = r >> 3, c = r & 7;
            int co = cotile * 8 + po;
            int ci0 = c * 8 + cpl * 2;
            int cog = ms * 32 + co;
            float f0 = 0.f, f1 = 0.f;
            if (cog < COUT) {
                const float* wp = wgt + ((size_t)cog * 64 + ci0) * 9 + t;
                f0 = __ldg(wp);
                f1 = __ldg(wp + 9);
            }
            uint32_t h = packh2(f0, f1);
            uint32_t off = (uint32_t)(ms * A_PLANE + (t * 32 + co) * 128 +
                                      ((c ^ (co & 7)) << 4) + cpl * 4);
            asm volatile("st.shared.b32 [%0], %1;" :: "r"(sb + off), "r"(h) : "memory");
        }
    }

    // ---- B row-plane stage: plane row yy -> slot (yy+NSLOT)%NSLOT ----
    auto stage_B = [&](int yy) {
        const int slot = (yy + NSLOT) % NSLOT;
        const bool ok_row = (yy >= 0) && (yy < HH);
        const unsigned short* src = reinterpret_cast<const unsigned short*>(
            in + ((size_t)b * 64 * HH + (ok_row ? yy : 0)) * WW);
        const int cpl = lane & 3, po = lane >> 2;
        const uint32_t bH = sb + OFFB + slot * B_PLANE;
        for (int it = warp; it < 136; it += NWARPS) {
            int c = it & 7, pxt = it >> 3;
            int px = pxt * 8 + po;
            if (px >= 132) continue;
            int ci0 = c * 8 + cpl * 2;
            int gx = x0 - 1 + px;
            bool ok = ok_row && (gx >= 0) && (gx < WW);
            const unsigned short* p = src + (size_t)ci0 * HWSZ + (ok ? gx : 0);
            uint32_t s0 = ok ? (uint32_t)__ldg(p) : 0u;
            uint32_t s1 = ok ? (uint32_t)__ldg(p + HWSZ) : 0u;
            uint32_t hi = s0 | (s1 << 16);
            uint32_t off = (uint32_t)(px * 128 + ((c ^ (px & 7)) << 4) + cpl * 4);
            asm volatile("st.shared.b32 [%0], %1;" :: "r"(bH + off), "r"(hi) : "memory");
        }
    };

    // initial fill: planes y0-1 .. y0+4
    for (int i = -1; i <= 4; i++) stage_B(y0 + i);
    __syncthreads();

    const int r7 = lane & 7, g = lane >> 3;
    const int a_row = wy * 16 + r7 + ((g & 1) << 3);  // co row within 32
    const int a_kh = g >> 1;
    const int b_noff = r7;
    const int b_kh = g & 1;
    const int nb = wx * 8;
    const int row_d = lane >> 2, col_d = (lane & 3) * 2;

    const int yend = y0 + RPC;
#pragma unroll 1
    for (int y = y0; y < yend; y += RPI) {
        // plane slots: index i = input row (y-1+i), i=0..5
        uint32_t plH[NSLOT];
#pragma unroll
        for (int i = 0; i < NSLOT; i++)
            plH[i] = sb + OFFB + ((y - 1 + i + NSLOT * 64) % NSLOT) * B_PLANE;

#pragma unroll 1
        for (int ms = 0; ms < NSLICE; ms++) {
            const uint32_t aBase = sb + (uint32_t)(ms * A_PLANE);
            const int co_base = ms * 32;

            float acc[RPI][4];
#pragma unroll
            for (int r = 0; r < RPI; r++)
#pragma unroll
                for (int j = 0; j < 4; j++) acc[r][j] = 0.f;

#pragma unroll
            for (int kc = 0; kc < 4; kc++) {
#pragma unroll
                for (int dx = 0; dx < 3; dx++) {
                    const int pxm = nb + dx + b_noff;
                    const uint32_t bRow = (uint32_t)(pxm * 128);
                    const uint32_t cB =
                        (uint32_t)((((kc << 1) | b_kh) ^ (pxm & 7)) << 4);
                    // B n8 fragments for the 6 live planes (6 LDSM.x2)
                    uint32_t BF[NSLOT][2];
#pragma unroll
                    for (int pl = 0; pl < NSLOT; pl++)
                        ldmx2(BF[pl][0], BF[pl][1], plH[pl] + bRow + cB);
                    const uint32_t cA =
                        (uint32_t)((((kc << 1) | a_kh) ^ r7) << 4);
#pragma unroll
                    for (int dy = 0; dy < 3; dy++) {
                        const int t = dy * 3 + dx;
                        const uint32_t aHp = aBase + (uint32_t)(t * 32 * 128);
                        uint32_t AH[4];
                        ldmx4(AH[0], AH[1], AH[2], AH[3],
                              aHp + (uint32_t)(a_row * 128) + cA);
                        // row r uses plane (r + dy)
#pragma unroll
                        for (int r = 0; r < RPI; r++)
                            mma16816(acc[r], AH, BF[r + dy][0], BF[r + dy][1]);
                    }
                }
            }

            // epilogue for this slice (global only, no SMEM)
#pragma unroll
            for (int r = 0; r < RPI; r++) {
                const int yy = y + r;
                float* c = acc[r];
                int x = x0 + nb + col_d;
#pragma unroll
                for (int h = 0; h < 2; h++) {
                    int co = co_base + wy * 16 + row_d + h * 8;
                    if (co < COUT) {
                        float bv = __ldg(bias + co);
                        float v0 = c[2 * h] + bv, v1 = c[2 * h + 1] + bv;
                        if (RELU) { v0 = fmaxf(v0, 0.f); v1 = fmaxf(v1, 0.f); }
                        size_t idx =
                            (((size_t)b * COUT + co) * HH + yy) * WW + x;
                        if (PACK_OUT) {
                            __half2 hv = __floats2half2_rn(v0, v1);
                            *reinterpret_cast<__half2*>((__half*)outv + idx) = hv;
                        } else {
                            *reinterpret_cast<float2*>((float*)outv + idx) =
                                make_float2(v0, v1);
                        }
                    }
                }
            }
        }

        if (y + RPI < yend) {
            __syncthreads();
            stage_B(y + 5);
            stage_B(y + 6);
            stage_B(y + 7);
            stage_B(y + 8);
            __syncthreads();
        }
    }
}

// ======================= scalar conv1 (4 -> 64) =============================
__device__ __forceinline__ unsigned long long pack2(float x, float y) {
    unsigned long long r;
    asm("mov.b64 %0, {%1, %2};" : "=l"(r) : "f"(x), "f"(y));
    return r;
}
__device__ __forceinline__ unsigned long long bcast2(float x) { return pack2(x, x); }
__device__ __forceinline__ float2 unpack2(unsigned long long v) {
    float2 f;
    asm("mov.b64 {%0, %1}, %2;" : "=f"(f.x), "=f"(f.y) : "l"(v));
    return f;
}
__device__ __forceinline__ unsigned long long ffma2(unsigned long long a,
                                                    unsigned long long b,
                                                    unsigned long long c) {
    unsigned long long d;
    asm("fma.rn.f32x2 %0, %1, %2, %3;" : "=l"(d) : "l"(a), "l"(b), "l"(c));
    return d;
}

__global__ __launch_bounds__(512, 1)
void conv1_kernel(const float* __restrict__ rgb, const float* __restrict__ depth,
                  const float* __restrict__ wgt, const float* __restrict__ bias,
                  __half* __restrict__ out) {
    constexpr int QS = 16, PIX = 4, CCH = 4;
    constexpr int NP = 8, NP2 = 4;
    __shared__ __align__(16) float ws[CCH][9][4][QS];

    const int tid = threadIdx.x;
    const int lx = tid & 31;
    const int ty = (tid >> 5) & 3;
    const int q = tid >> 7;
    const int x = blockIdx.x * 32 + lx;
    const int y0 = blockIdx.y * (4 * PIX) + ty * PIX;
    const int b = blockIdx.z;
    const int co0 = q * QS;

    unsigned long long acc[PIX][NP];
#pragma unroll
    for (int pr = 0; pr < NP; pr++) {
        unsigned long long bb = pack2(__ldg(bias + co0 + 2 * pr),
                                      __ldg(bias + co0 + 2 * pr + 1));
#pragma unroll
        for (int p = 0; p < PIX; p++) acc[p][pr] = bb;
    }

    int rowoff[PIX + 2];
    bool rok[PIX + 2];
#pragma unroll
    for (int r = 0; r < PIX + 2; r++) {
        int yy = y0 - 1 + r;
        rok[r] = (yy >= 0) && (yy < HH);
        rowoff[r] = yy * WW;
    }
    const bool xok0 = (x > 0), xok2 = (x < WW - 1);

    for (int i = tid; i < CCH * 9 * 4 * QS; i += 512) {
        int col = i % QS;
        int qq = (i / QS) % 4;
        int t = (i / (QS * 4)) % 9;
        int cl = i / (QS * 4 * 9);
        (&ws[0][0][0][0])[i] = __ldg(wgt + ((size_t)(qq * QS + col) * 4 + cl) * 9 + t);
    }
    __syncthreads();

#pragma unroll
    for (int ci = 0; ci < 4; ci++) {
        const float* ip = (ci < 3) ? (rgb + ((size_t)b * 3 + ci) * HWSZ)
                                   : (depth + (size_t)b * HWSZ);
        const float* ipx = ip + x;
        float v[PIX + 2][3];
#pragma unroll
        for (int r = 0; r < PIX + 2; r++) {
            v[r][0] = (rok[r] && xok0) ? __ldg(ipx + rowoff[r] - 1) : 0.f;
            v[r][1] = rok[r] ? __ldg(ipx + rowoff[r]) : 0.f;
            v[r][2] = (rok[r] && xok2) ? __ldg(ipx + rowoff[r] + 1) : 0.f;
        }
#pragma unroll
        for (int dy = 0; dy < 3; dy++) {
#pragma unroll
            for (int dx = 0; dx < 3; dx++) {
                const ulonglong2* wp =
                    reinterpret_cast<const ulonglong2*>(&ws[ci][dy * 3 + dx][q][0]);
                ulonglong2 wq[NP2];
#pragma unroll
                for (int j = 0; j < NP2; j++) wq[j] = wp[j];
#pragma unroll
                for (int p = 0; p < PIX; p++) {
                    unsigned long long vv = bcast2(v[p + dy][dx]);
#pragma unroll
                    for (int j = 0; j < NP2; j++) {
                        acc[p][2 * j] = ffma2(vv, wq[j].x, acc[p][2 * j]);
                        acc[p][2 * j + 1] = ffma2(vv, wq[j].y, acc[p][2 * j + 1]);
                    }
                }
            }
        }
    }

#pragma unroll
    for (int p = 0; p < PIX; p++) {
        size_t base = ((size_t)b * 64) * HWSZ + (size_t)(y0 + p) * WW + x;
#pragma unroll
        for (int pr = 0; pr < NP; pr++) {
            float2 f = unpack2(acc[p][pr]);
            f.x = fmaxf(f.x, 0.f);
            f.y = fmaxf(f.y, 0.f);
            int co = co0 + 2 * pr;
            out[base + (size_t)co * HWSZ] = __float2half_rn(f.x);
            out[base + (size_t)(co + 1) * HWSZ] = __float2half_rn(f.y);
        }
    }
}

// ======================= softmax + bokeh ====================================
__global__ __launch_bounds__(128, 4)
void softmax_bokeh_kernel(const float* __restrict__ logits,
                          const float* __restrict__ rgb,
                          float* __restrict__ out) {
    __shared__ float tile[3][12][40];
    const int tid = threadIdx.x;
    const int lx = tid & 31;
    const int ty = tid >> 5;
    const int x = blockIdx.x * 32 + lx;
    const int y = blockIdx.y * 4 + ty;
    const int b = blockIdx.z;
    const int gx0 = blockIdx.x * 32 - 4;
    const int gy0 = blockIdx.y * 4 - 4;

    for (int i = tid; i < 3 * 12 * 40; i += 128) {
        int xx = i % 40;
        int yy = (i / 40) % 12;
        int c = i / 480;
        int gx = gx0 + xx, gy = gy0 + yy;
        float v = 0.f;
        if (gx >= 0 && gx < WW && gy >= 0 && gy < HH)
            v = rgb[((size_t)b * 3 + c) * HWSZ + (size_t)gy * WW + gx];
        tile[c][yy][xx] = v;
    }
    __syncthreads();

    float lg[81];
    const float* lp = logits + (size_t)b * 81 * HWSZ + (size_t)y * WW + x;
    float m = -1e30f;
#pragma unroll
    for (int t = 0; t < 81; t++) {
        lg[t] = __ldg(lp + (size_t)t * HWSZ);
        m = fmaxf(m, lg[t]);
    }
    float s = 0.f;
#pragma unroll
    for (int t = 0; t < 81; t++) {
        float e = __expf(lg[t] - m);
        lg[t] = e;
        s += e;
    }
    float inv = 1.f / s;

    float r = 0.f, g = 0.f, bl = 0.f;
#pragma unroll
    for (int dy = 0; dy < 9; dy++) {
#pragma unroll
        for (int dx = 0; dx < 9; dx++) {
            float f = lg[dy * 9 + dx] * inv;
            r += f * tile[0][ty + dy][lx + dx];
            g += f * tile[1][ty + dy][lx + dx];
            bl += f * tile[2][ty + dy][lx + dx];
        }
    }
    size_t ob = (size_t)b * 3 * HWSZ + (size_t)y * WW + x;
    out[ob] = r;
    out[ob + HWSZ] = g;
    out[ob + 2 * HWSZ] = bl;
}

// ======================= launch =============================================
extern "C" void kernel_launch(void* const* d_in, const int* in_sizes, int n_in,
                              void* d_out, int out_size) {
    const float* rgb   = (const float*)d_in[0];
    const float* depth = (const float*)d_in[1];
    const float* w1    = (const float*)d_in[2];
    const float* b1    = (const float*)d_in[3];
    const float* w2    = (const float*)d_in[4];
    const float* b2    = (const float*)d_in[5];
    const float* w3    = (const float*)d_in[6];
    const float* b3    = (const float*)d_in[7];
    float* out = (float*)d_out;

    __half *h1, *h2;
    float* lg;
    cudaGetSymbolAddress((void**)&h1, g_h1);
    cudaGetSymbolAddress((void**)&h2, g_h2);
    cudaGetSymbolAddress((void**)&lg, g_logits);

    const int smem2 = 2 * A_PLANE + NSLOT * B_PLANE;  // 175104
    const int smem3 = 3 * A_PLANE + NSLOT * B_PLANE;  // 211968
    cudaFuncSetAttribute(conv3x3_hmma<64, 2, true, true>,
                         cudaFuncAttributeMaxDynamicSharedMemorySize, smem2);
    cudaFuncSetAttribute(conv3x3_hmma<81, 3, false, false>,
                         cudaFuncAttributeMaxDynamicSharedMemorySize, smem3);

    // conv1: scalar FFMA2, writes fp16 h1
    conv1_kernel<<<dim3(WW / 32, HH / 16, BATCH), 512>>>(rgb, depth, w1, b1, h1);
    // conv2: HMMA implicit GEMM, 2 slices per CTA (input staged once)
    conv3x3_hmma<64, 2, true, true><<<dim3(WW / NPX, HH / RPC, BATCH),
                                      NTHREADS, smem2>>>(h1, w2, b2, h2);
    // conv3: HMMA implicit GEMM, 3 slices per CTA (81 real channels)
    conv3x3_hmma<81, 3, false, false><<<dim3(WW / NPX, HH / RPC, BATCH),
                                        NTHREADS, smem3>>>(h2, w3, b3, lg);
    // softmax + bokeh
    softmax_bokeh_kernel<<<dim3(WW / 32, HH / 4, BATCH), 128>>>(lg, rgb, out);
}